// round 4
// baseline (speedup 1.0000x reference)
#include <cuda_runtime.h>
#include <math.h>

#define D 512
#define V 17
#define MAX_SEGS 64
#define NSUB 2
#define EPAD 20      // padded row stride for transposed A table (80B, 16B-aligned)

// Scratch (allocation-free, graph-safe).
__device__ float g_mid[V * D];                 // gelu(E@W1+b1)
__device__ int   g_cnt[MAX_SEGS * NSUB * V];   // partial histograms

// Shared scratch union (40960 B max member).
union SmemU {
    float etr[D * EPAD];        // transposed A: etr[k*EPAD + v]   (40960 B)
    float red[16 * V * 32];     // split-k reduction buffer        (34816 B)
    int   cnt[16 * 32];         // per-warp histograms
};

// ---------------------------------------------------------------------------
// GEMM tile: acc[v] = sum over this thread's 32-k slice of A[v][k]*W[k][j].
// A staged transposed in smem; W prefetched into 32 registers (MLP=32).
// ---------------------------------------------------------------------------
__device__ __forceinline__ void gemm_core(SmemU& sm,
                                          const float* __restrict__ A,
                                          const float* __restrict__ W,
                                          int jtile, float acc[V]) {
    const int tid = threadIdx.x;
    const int tx = tid & 31;
    const int ty = tid >> 5;

    // stage A (17 x 512) transposed -> etr[k][v]
    for (int i = tid; i < V * D; i += 512) {
        const int v = i >> 9;
        const int k = i & 511;
        sm.etr[k * EPAD + v] = A[i];
    }
    __syncthreads();

#pragma unroll
    for (int v = 0; v < V; v++) acc[v] = 0.0f;

    const int k0 = ty * 32;
    const float* wp = W + (size_t)k0 * D + jtile * 32 + tx;

    float w[32];
#pragma unroll
    for (int kk = 0; kk < 32; kk++) w[kk] = wp[kk * D];

#pragma unroll
    for (int kk = 0; kk < 32; kk++) {
        const float* er = &sm.etr[(k0 + kk) * EPAD];
        const float4 e0 = *(const float4*)(er);
        const float4 e1 = *(const float4*)(er + 4);
        const float4 e2 = *(const float4*)(er + 8);
        const float4 e3 = *(const float4*)(er + 12);
        const float  ee = er[16];
        const float  wv = w[kk];
        acc[0]  += e0.x * wv;  acc[1]  += e0.y * wv;
        acc[2]  += e0.z * wv;  acc[3]  += e0.w * wv;
        acc[4]  += e1.x * wv;  acc[5]  += e1.y * wv;
        acc[6]  += e1.z * wv;  acc[7]  += e1.w * wv;
        acc[8]  += e2.x * wv;  acc[9]  += e2.y * wv;
        acc[10] += e2.z * wv;  acc[11] += e2.w * wv;
        acc[12] += e3.x * wv;  acc[13] += e3.y * wv;
        acc[14] += e3.z * wv;  acc[15] += e3.w * wv;
        acc[16] += ee   * wv;
    }
    __syncthreads();   // done reading etr; red aliases it

#pragma unroll
    for (int v = 0; v < V; v++) sm.red[(ty * V + v) * 32 + tx] = acc[v];
    __syncthreads();
}

// ---------------------------------------------------------------------------
// Kernel 1: CTAs 0..15: g_mid = gelu(E@W1+b1).  CTAs 16..: partial histograms.
// Grid = 16 + NSUB*n_segs = 144 -> single wave.
// ---------------------------------------------------------------------------
__global__ void __launch_bounds__(512, 1)
k1(const float* __restrict__ E, const float* __restrict__ W1,
   const float* __restrict__ b1, const int* __restrict__ tok,
   const int* __restrict__ cu, int n_segs) {
    __shared__ SmemU sm;
    const int bid = blockIdx.x;
    const int tid = threadIdx.x;

    if (bid < 16) {
        float acc[V];
        gemm_core(sm, E, W1, bid, acc);
        // reduce 16 k-slices, add bias, gelu, store
        for (int o = tid; o < V * 32; o += 512) {
            const int v = o >> 5;
            const int t = o & 31;
            float s = b1[bid * 32 + t];
#pragma unroll
            for (int sl = 0; sl < 16; sl++) s += sm.red[(sl * V + v) * 32 + t];
            s = 0.5f * s * (1.0f + erff(s * 0.70710678118654752f));
            g_mid[v * D + bid * 32 + t] = s;
        }
        return;
    }

    const int h = bid - 16;
    const int s = h >> 1;          // NSUB == 2
    const int sub = h & 1;
    if (s >= n_segs) return;

    const int start = cu[s];
    const int end = cu[s + 1];
    const int len = end - start;
    const int q = (len + NSUB - 1) >> 1;
    const int lo = start + sub * q;
    const int hi = min(lo + q, end);
    const int wid = tid >> 5;

    for (int i = tid; i < 16 * 32; i += 512) sm.cnt[i] = 0;
    __syncthreads();

    for (int i = lo + tid; i < hi; i += 512)
        atomicAdd(&sm.cnt[wid * 32 + tok[i]], 1);
    __syncthreads();

    if (tid < V) {
        int c = 0;
#pragma unroll
        for (int w = 0; w < 16; w++) c += sm.cnt[w * 32 + tid];
        g_cnt[(s * NSUB + sub) * V + tid] = c;
    }
}

// ---------------------------------------------------------------------------
// Kernel 2 (fused): H-tile = g_mid@W2 + b2 for this CTA's 32 columns, kept in
// smem; then out[s][j] = (sum_v cnt[s][v]*H[v][j]) / len_s for all segments.
// ---------------------------------------------------------------------------
__global__ void __launch_bounds__(512, 1)
k2(const float* __restrict__ W2, const float* __restrict__ b2,
   const int* __restrict__ cu, float* __restrict__ out, int n_segs) {
    __shared__ SmemU sm;
    __shared__ float htile[V * 32];
    __shared__ float fc[MAX_SEGS * (V + 1)];   // padded stride 18
    __shared__ float inv[MAX_SEGS];

    const int bid = blockIdx.x;
    const int tid = threadIdx.x;
    const int tx = tid & 31;
    const int ty = tid >> 5;

    float acc[V];
    gemm_core(sm, g_mid, W2, bid, acc);

    // combined counts + inverse lengths (g_cnt produced by k1)
    for (int i = tid; i < n_segs * V; i += 512) {
        const int s = i / V;
        const int v = i - s * V;
        fc[s * (V + 1) + v] =
            (float)(g_cnt[(s * NSUB + 0) * V + v] + g_cnt[(s * NSUB + 1) * V + v]);
    }
    if (tid < n_segs) inv[tid] = 1.0f / (float)(cu[tid + 1] - cu[tid]);

    // reduce k-slices into registers (<=2 outputs per thread)
    float hv[2];
    int   ho[2] = {-1, -1};
    int   nh = 0;
    for (int o = tid; o < V * 32; o += 512) {
        const int v = o >> 5;
        const int t = o & 31;
        float s = b2[bid * 32 + t];
#pragma unroll
        for (int sl = 0; sl < 16; sl++) s += sm.red[(sl * V + v) * 32 + t];
        hv[nh] = s; ho[nh] = o; nh++;
    }
    __syncthreads();
    for (int i = 0; i < nh; i++) htile[ho[i]] = hv[i];
    __syncthreads();

    // mix: thread (tx=j, ty) handles segments ty*4 + r
#pragma unroll
    for (int r = 0; r < 4; r++) {
        const int s = ty * 4 + r;
        if (s >= n_segs) break;
        const float* f = &fc[s * (V + 1)];
        float a = 0.0f;
#pragma unroll
        for (int v = 0; v < V; v++) a += f[v] * htile[v * 32 + tx];
        out[s * D + bid * 32 + tx] = a * inv[s];
    }
}

// ---------------------------------------------------------------------------
extern "C" void kernel_launch(void* const* d_in, const int* in_sizes, int n_in,
                              void* d_out, int out_size) {
    const int*   tok = (const int*)  d_in[0];
    const int*   cu  = (const int*)  d_in[1];
    const float* E   = (const float*)d_in[2];
    const float* W1  = (const float*)d_in[3];
    const float* b1  = (const float*)d_in[4];
    const float* W2  = (const float*)d_in[5];
    const float* b2  = (const float*)d_in[6];
    float*       out = (float*)d_out;

    int n_segs = in_sizes[1] - 1;
    if (n_segs > MAX_SEGS) n_segs = MAX_SEGS;

    k1<<<16 + NSUB * n_segs, 512>>>(E, W1, b1, tok, cu, n_segs);
    k2<<<16, 512>>>(W2, b2, cu, out, n_segs);
}

// round 6
// speedup vs baseline: 1.5129x; 1.5129x over previous
#include <cuda_runtime.h>
#include <math.h>

#define D 512
#define V 17
#define MAX_SEGS 64
#define EPAD 20
#define KS 4            // k-slices per GEMM
#define KSL 128         // k elements per slice
#define TPB 512

// Scratch (allocation-free, graph-safe).
__device__ float g_part1[KS][V][D];     // partial E@W1
__device__ float g_part2[KS][V][D];     // partial gelu(...)@W2
__device__ int   g_hist[MAX_SEGS][V];   // per-segment token counts

union SmemU {
    float etr[KSL * EPAD];      // transposed A k-slice: etr[kl*EPAD+v] (10240B)
    float red[16 * V * 32];     // split-slice reduction buffer       (34816B)
    int   cnt[16 * 32];         // per-warp histograms
};

// ---------------------------------------------------------------------------
// Split-K GEMM slice: CTA covers 32 j-columns (jt) and 128 k (ks).
// sm.etr must already hold A[v][k] transposed for this k-slice.
// Result: out_part[ks][v][jt*32+t] = partial sums (16 sub-slices reduced).
// ---------------------------------------------------------------------------
__device__ __forceinline__ void gemm_slice(SmemU& sm,
                                           const float* __restrict__ W,
                                           int jt, int ks,
                                           float out_part[KS][V][D]) {
    const int tid = threadIdx.x;
    const int tx = tid & 31;
    const int ty = tid >> 5;

    float acc[V];
#pragma unroll
    for (int v = 0; v < V; v++) acc[v] = 0.0f;

    const float* wp = W + (size_t)(ks * KSL + ty * 8) * D + jt * 32 + tx;
    float w[8];
#pragma unroll
    for (int kk = 0; kk < 8; kk++) w[kk] = wp[kk * D];

#pragma unroll
    for (int kk = 0; kk < 8; kk++) {
        const float* er = &sm.etr[(ty * 8 + kk) * EPAD];
        const float4 e0 = *(const float4*)(er);
        const float4 e1 = *(const float4*)(er + 4);
        const float4 e2 = *(const float4*)(er + 8);
        const float4 e3 = *(const float4*)(er + 12);
        const float  ee = er[16];
        const float  wv = w[kk];
        acc[0]  += e0.x * wv;  acc[1]  += e0.y * wv;
        acc[2]  += e0.z * wv;  acc[3]  += e0.w * wv;
        acc[4]  += e1.x * wv;  acc[5]  += e1.y * wv;
        acc[6]  += e1.z * wv;  acc[7]  += e1.w * wv;
        acc[8]  += e2.x * wv;  acc[9]  += e2.y * wv;
        acc[10] += e2.z * wv;  acc[11] += e2.w * wv;
        acc[12] += e3.x * wv;  acc[13] += e3.y * wv;
        acc[14] += e3.z * wv;  acc[15] += e3.w * wv;
        acc[16] += ee   * wv;
    }
    __syncthreads();      // done reading etr; red aliases it

#pragma unroll
    for (int v = 0; v < V; v++) sm.red[(ty * V + v) * 32 + tx] = acc[v];
    __syncthreads();

    for (int o = tid; o < V * 32; o += TPB) {
        const int v = o >> 5;
        const int t = o & 31;
        float s = 0.0f;
#pragma unroll
        for (int sl = 0; sl < 16; sl++) s += sm.red[(sl * V + v) * 32 + t];
        out_part[ks][v][jt * 32 + t] = s;
    }
}

// ---------------------------------------------------------------------------
// k1: CTAs 0..63: partial GEMM1 (E@W1). CTAs 64..64+n_segs-1: histograms.
// 128 CTAs total -> single wave.
// ---------------------------------------------------------------------------
__global__ void __launch_bounds__(TPB, 1)
k1(const float* __restrict__ E, const float* __restrict__ W1,
   const int* __restrict__ tok, const int* __restrict__ cu, int n_segs) {
    __shared__ SmemU sm;
    const int bid = blockIdx.x;
    const int tid = threadIdx.x;

    if (bid < 64) {
        const int jt = bid >> 2;
        const int ks = bid & 3;
        for (int i = tid; i < V * KSL; i += TPB) {
            const int v = i >> 7;
            const int kl = i & (KSL - 1);
            sm.etr[kl * EPAD + v] = E[v * D + ks * KSL + kl];
        }
        __syncthreads();
        gemm_slice(sm, W1, jt, ks, g_part1);
        return;
    }

    const int s = bid - 64;
    if (s >= n_segs) return;
    const int start = cu[s];
    const int end = cu[s + 1];
    const int wid = tid >> 5;

    for (int i = tid; i < 16 * 32; i += TPB) sm.cnt[i] = 0;
    __syncthreads();
    for (int i = start + tid; i < end; i += TPB)
        atomicAdd(&sm.cnt[wid * 32 + tok[i]], 1);
    __syncthreads();
    if (tid < V) {
        int c = 0;
#pragma unroll
        for (int w = 0; w < 16; w++) c += sm.cnt[w * 32 + tid];
        g_hist[s][tid] = c;
    }
}

// ---------------------------------------------------------------------------
// k2: 64 CTAs. Finalize g_mid slice on the fly (sum 4 partials + b1 + gelu)
// while staging into smem, then partial GEMM2 into g_part2.
// ---------------------------------------------------------------------------
__global__ void __launch_bounds__(TPB, 1)
k2(const float* __restrict__ W2, const float* __restrict__ b1) {
    __shared__ SmemU sm;
    const int bid = blockIdx.x;
    const int tid = threadIdx.x;
    const int jt = bid >> 2;
    const int ks = bid & 3;

    for (int i = tid; i < V * KSL; i += TPB) {
        const int v = i >> 7;
        const int kl = i & (KSL - 1);
        const int k = ks * KSL + kl;
        float s = b1[k] + g_part1[0][v][k] + g_part1[1][v][k]
                        + g_part1[2][v][k] + g_part1[3][v][k];
        s = 0.5f * s * (1.0f + erff(s * 0.70710678118654752f));
        sm.etr[kl * EPAD + v] = s;
    }
    __syncthreads();
    gemm_slice(sm, W2, jt, ks, g_part2);
}

// ---------------------------------------------------------------------------
// k3: 64 CTAs, each owns 8 output columns. Finalize H (sum partials + b2),
// then out[s][j] = (sum_v cnt[s][v]*H[v][j]) / len_s. Thread = (seg, col).
// ---------------------------------------------------------------------------
__global__ void __launch_bounds__(TPB, 1)
k3(const float* __restrict__ b2, const int* __restrict__ cu,
   float* __restrict__ out, int n_segs) {
    __shared__ float Ht[V * 8];
    __shared__ float fcs[MAX_SEGS * 18];
    __shared__ float inv[MAX_SEGS];

    const int bid = blockIdx.x;
    const int tid = threadIdx.x;
    const int jbase = bid * 8;

    if (tid < V * 8) {
        const int v = tid >> 3;
        const int jl = tid & 7;
        const int j = jbase + jl;
        Ht[v * 8 + jl] = b2[j] + g_part2[0][v][j] + g_part2[1][v][j]
                               + g_part2[2][v][j] + g_part2[3][v][j];
    }
    for (int i = tid; i < n_segs * V; i += TPB) {
        const int s = i / V;
        const int v = i - s * V;
        fcs[s * 18 + v] = (float)g_hist[s][v];
    }
    if (tid < n_segs)
        inv[tid] = 1.0f / (float)(cu[tid + 1] - cu[tid]);
    __syncthreads();

    const int s = tid >> 3;
    const int jl = tid & 7;
    if (s < n_segs) {
        const float* f = &fcs[s * 18];
        float a = 0.0f;
#pragma unroll
        for (int v = 0; v < V; v++) a += f[v] * Ht[v * 8 + jl];
        out[s * D + jbase + jl] = a * inv[s];
    }
}

// ---------------------------------------------------------------------------
extern "C" void kernel_launch(void* const* d_in, const int* in_sizes, int n_in,
                              void* d_out, int out_size) {
    const int*   tok = (const int*)  d_in[0];
    const int*   cu  = (const int*)  d_in[1];
    const float* E   = (const float*)d_in[2];
    const float* W1  = (const float*)d_in[3];
    const float* b1  = (const float*)d_in[4];
    const float* W2  = (const float*)d_in[5];
    const float* b2  = (const float*)d_in[6];
    float*       out = (float*)d_out;

    int n_segs = in_sizes[1] - 1;
    if (n_segs > MAX_SEGS) n_segs = MAX_SEGS;

    k1<<<64 + n_segs, TPB>>>(E, W1, tok, cu, n_segs);
    k2<<<64, TPB>>>(W2, b1);
    k3<<<64, TPB>>>(b2, cu, out, n_segs);
}

// round 7
// speedup vs baseline: 1.5427x; 1.0197x over previous
#include <cuda_runtime.h>
#include <math.h>

#define D 512
#define V 17
#define MAX_SEGS 64
#define EPAD 20
#define KS 4            // k-slices per GEMM
#define KSL 128         // k elements per slice
#define TPB 512

// Scratch (allocation-free, graph-safe).
__device__ float g_part1[KS][V][D];     // partial E@W1
__device__ float g_part2[KS][V][D];     // partial gelu(mid)@W2
__device__ int   g_hist[MAX_SEGS][V];   // per-segment token counts
__device__ int   g_done[16];            // per-jt completion counters (zero-init)

union SmemU {
    float etr[KSL * EPAD];      // transposed A k-slice: etr[kl*EPAD+v]
    float red[16 * V * 32];     // split-slice reduction buffer (34816B max)
    int   cnt[16 * 32];         // per-warp histograms
    struct {
        float Ht[V * 32];           // finalized H tile (17 x 32 cols)
        float fcs[MAX_SEGS * 18];   // per-seg counts (padded stride 18)
        float inv[MAX_SEGS];
    } p3;
};

// ---------------------------------------------------------------------------
// Split-K GEMM slice: 32 j-cols (jt), 128 k (ks). sm.etr holds A transposed.
// ---------------------------------------------------------------------------
__device__ __forceinline__ void gemm_slice(SmemU& sm,
                                           const float* __restrict__ W,
                                           int jt, int ks,
                                           float out_part[KS][V][D]) {
    const int tid = threadIdx.x;
    const int tx = tid & 31;
    const int ty = tid >> 5;

    float acc[V];
#pragma unroll
    for (int v = 0; v < V; v++) acc[v] = 0.0f;

    const float* wp = W + (size_t)(ks * KSL + ty * 8) * D + jt * 32 + tx;
    float w[8];
#pragma unroll
    for (int kk = 0; kk < 8; kk++) w[kk] = wp[kk * D];

#pragma unroll
    for (int kk = 0; kk < 8; kk++) {
        const float* er = &sm.etr[(ty * 8 + kk) * EPAD];
        const float4 e0 = *(const float4*)(er);
        const float4 e1 = *(const float4*)(er + 4);
        const float4 e2 = *(const float4*)(er + 8);
        const float4 e3 = *(const float4*)(er + 12);
        const float  ee = er[16];
        const float  wv = w[kk];
        acc[0]  += e0.x * wv;  acc[1]  += e0.y * wv;
        acc[2]  += e0.z * wv;  acc[3]  += e0.w * wv;
        acc[4]  += e1.x * wv;  acc[5]  += e1.y * wv;
        acc[6]  += e1.z * wv;  acc[7]  += e1.w * wv;
        acc[8]  += e2.x * wv;  acc[9]  += e2.y * wv;
        acc[10] += e2.z * wv;  acc[11] += e2.w * wv;
        acc[12] += e3.x * wv;  acc[13] += e3.y * wv;
        acc[14] += e3.z * wv;  acc[15] += e3.w * wv;
        acc[16] += ee   * wv;
    }
    __syncthreads();      // done reading etr; red aliases it

#pragma unroll
    for (int v = 0; v < V; v++) sm.red[(ty * V + v) * 32 + tx] = acc[v];
    __syncthreads();

    for (int o = tid; o < V * 32; o += TPB) {
        const int v = o >> 5;
        const int t = o & 31;
        float s = 0.0f;
#pragma unroll
        for (int sl = 0; sl < 16; sl++) s += sm.red[(sl * V + v) * 32 + t];
        out_part[ks][v][jt * 32 + t] = s;
    }
}

// ---------------------------------------------------------------------------
// k1: CTAs 0..63: partial GEMM1. CTAs 64..: histograms. Single wave (128 CTAs).
// ---------------------------------------------------------------------------
__global__ void __launch_bounds__(TPB, 1)
k1(const float* __restrict__ E, const float* __restrict__ W1,
   const int* __restrict__ tok, const int* __restrict__ cu, int n_segs) {
    __shared__ SmemU sm;
    const int bid = blockIdx.x;
    const int tid = threadIdx.x;

    if (bid < 64) {
        const int jt = bid >> 2;
        const int ks = bid & 3;
        // stage E k-slice transposed; one float4 LDG per thread (single latency)
        const float4* E4 = (const float4*)E;
        if (tid < V * 32) {
            const int v = tid >> 5;
            const int q = tid & 31;
            const float4 e = E4[v * (D / 4) + ks * 32 + q];
            const int kl = q * 4;
            sm.etr[(kl + 0) * EPAD + v] = e.x;
            sm.etr[(kl + 1) * EPAD + v] = e.y;
            sm.etr[(kl + 2) * EPAD + v] = e.z;
            sm.etr[(kl + 3) * EPAD + v] = e.w;
        }
        // thread of CTA 0 only: remaining 32 elements (544 > 512)
        if (tid < V * 32 - TPB) {
            const int i = TPB + tid;
            const int v = i >> 5;
            const int q = i & 31;
            const float4 e = E4[v * (D / 4) + ks * 32 + q];
            const int kl = q * 4;
            sm.etr[(kl + 0) * EPAD + v] = e.x;
            sm.etr[(kl + 1) * EPAD + v] = e.y;
            sm.etr[(kl + 2) * EPAD + v] = e.z;
            sm.etr[(kl + 3) * EPAD + v] = e.w;
        }
        __syncthreads();
        gemm_slice(sm, W1, jt, ks, g_part1);
        return;
    }

    const int s = bid - 64;
    if (s >= n_segs) return;
    const int start = cu[s];
    const int end = cu[s + 1];
    const int wid = tid >> 5;

    for (int i = tid; i < 16 * 32; i += TPB) sm.cnt[i] = 0;
    __syncthreads();

    // 4 independent loads per thread per round -> one exposed latency
    for (int base = start + tid * 4; base < end; base += TPB * 4) {
        int t0 = -1, t1 = -1, t2 = -1, t3 = -1;
        if (base + 0 < end) t0 = tok[base + 0];
        if (base + 1 < end) t1 = tok[base + 1];
        if (base + 2 < end) t2 = tok[base + 2];
        if (base + 3 < end) t3 = tok[base + 3];
        if (t0 >= 0) atomicAdd(&sm.cnt[wid * 32 + t0], 1);
        if (t1 >= 0) atomicAdd(&sm.cnt[wid * 32 + t1], 1);
        if (t2 >= 0) atomicAdd(&sm.cnt[wid * 32 + t2], 1);
        if (t3 >= 0) atomicAdd(&sm.cnt[wid * 32 + t3], 1);
    }
    __syncthreads();
    if (tid < V) {
        int c = 0;
#pragma unroll
        for (int w = 0; w < 16; w++) c += sm.cnt[w * 32 + tid];
        g_hist[s][tid] = c;
    }
}

// ---------------------------------------------------------------------------
// k2: 64 CTAs (jt x ks). Finalize mid slice (4 parallel partial reads + b1 +
// exact GELU) while staging, partial GEMM2, then the LAST CTA of each jt group
// finalizes H and does the histogram mix -> out (threadFenceReduction idiom).
// ---------------------------------------------------------------------------
__global__ void __launch_bounds__(TPB, 1)
k2(const float* __restrict__ W2, const float* __restrict__ b1,
   const float* __restrict__ b2, const int* __restrict__ cu,
   const float* __restrict__ unused, float* __restrict__ out, int n_segs) {
    __shared__ SmemU sm;
    __shared__ int sm_last;
    const int bid = blockIdx.x;
    const int tid = threadIdx.x;
    const int jt = bid >> 2;
    const int ks = bid & 3;

    // stage finalized gelu(mid) slice; all global reads independent
    {
        const float4* P0 = (const float4*)&g_part1[0][0][0];
        const float4* P1 = (const float4*)&g_part1[1][0][0];
        const float4* P2 = (const float4*)&g_part1[2][0][0];
        const float4* P3 = (const float4*)&g_part1[3][0][0];
        const float4* B1 = (const float4*)b1;
        for (int i = tid; i < V * 32; i += TPB) {
            const int v = i >> 5;
            const int q = i & 31;
            const int idx = v * (D / 4) + ks * 32 + q;   // float4 idx in [V][D]
            const float4 a = P0[idx];
            const float4 b = P1[idx];
            const float4 c = P2[idx];
            const float4 d = P3[idx];
            const float4 bb = B1[ks * 32 + q];
            float x0 = bb.x + a.x + b.x + c.x + d.x;
            float x1 = bb.y + a.y + b.y + c.y + d.y;
            float x2 = bb.z + a.z + b.z + c.z + d.z;
            float x3 = bb.w + a.w + b.w + c.w + d.w;
            x0 = 0.5f * x0 * (1.0f + erff(x0 * 0.70710678118654752f));
            x1 = 0.5f * x1 * (1.0f + erff(x1 * 0.70710678118654752f));
            x2 = 0.5f * x2 * (1.0f + erff(x2 * 0.70710678118654752f));
            x3 = 0.5f * x3 * (1.0f + erff(x3 * 0.70710678118654752f));
            const int kl = q * 4;
            sm.etr[(kl + 0) * EPAD + v] = x0;
            sm.etr[(kl + 1) * EPAD + v] = x1;
            sm.etr[(kl + 2) * EPAD + v] = x2;
            sm.etr[(kl + 3) * EPAD + v] = x3;
        }
    }
    __syncthreads();
    gemm_slice(sm, W2, jt, ks, g_part2);

    // completion protocol
    __threadfence();
    __syncthreads();
    if (tid == 0) {
        const int t = atomicAdd(&g_done[jt], 1);
        sm_last = (t == KS - 1);
        if (t == KS - 1) g_done[jt] = 0;   // self-reset for next graph replay
    }
    __syncthreads();
    if (!sm_last) return;

    // ---- mix (last CTA of this jt group): finalize H, apply counts ----
    for (int i = tid; i < V * 32; i += TPB) {
        const int v = i >> 5;
        const int t = i & 31;
        const int j = jt * 32 + t;
        sm.p3.Ht[v * 32 + t] = b2[j] + g_part2[0][v][j] + g_part2[1][v][j]
                                     + g_part2[2][v][j] + g_part2[3][v][j];
    }
    for (int i = tid; i < n_segs * V; i += TPB) {
        const int s = i / V;
        const int v = i - s * V;
        sm.p3.fcs[s * 18 + v] = (float)g_hist[s][v];
    }
    if (tid < n_segs)
        sm.p3.inv[tid] = 1.0f / (float)(cu[tid + 1] - cu[tid]);
    __syncthreads();

    const int tx = tid & 31;
    const int s0 = tid >> 5;
#pragma unroll
    for (int r = 0; r < 4; r++) {
        const int s = s0 + 16 * r;
        if (s < n_segs) {
            const float* f = &sm.p3.fcs[s * 18];
            float a = 0.0f;
#pragma unroll
            for (int v = 0; v < V; v++) a += f[v] * sm.p3.Ht[v * 32 + tx];
            out[s * D + jt * 32 + tx] = a * sm.p3.inv[s];
        }
    }
}

// ---------------------------------------------------------------------------
extern "C" void kernel_launch(void* const* d_in, const int* in_sizes, int n_in,
                              void* d_out, int out_size) {
    const int*   tok = (const int*)  d_in[0];
    const int*   cu  = (const int*)  d_in[1];
    const float* E   = (const float*)d_in[2];
    const float* W1  = (const float*)d_in[3];
    const float* b1  = (const float*)d_in[4];
    const float* W2  = (const float*)d_in[5];
    const float* b2  = (const float*)d_in[6];
    float*       out = (float*)d_out;

    int n_segs = in_sizes[1] - 1;
    if (n_segs > MAX_SEGS) n_segs = MAX_SEGS;

    k1<<<64 + n_segs, TPB>>>(E, W1, tok, cu, n_segs);
    k2<<<64, TPB>>>(W2, b1, b2, cu, (const float*)0, out, n_segs);
}

// round 9
// speedup vs baseline: 1.6947x; 1.0986x over previous
#include <cuda_runtime.h>
#include <math.h>

#define D 512
#define V 17
#define MAX_SEGS 64
#define EPAD 20
#define KS 4            // k-slices in GEMM1
#define KSL 128
#define TPB 512

// Scratch (allocation-free, graph-safe, zero-initialized).
__device__ float g_part1[KS][V][D];        // partial E@W1
__device__ float g_midT[D * EPAD];         // finalized gelu-mid, transposed+padded
__device__ int   g_hist[MAX_SEGS][V];      // per-segment token counts

// k1 shared scratch (max member 34816 B)
union SmemU {
    float etr[KSL * EPAD];      // transposed E k-slice (10240B)
    float red[16 * V * 32];     // split-slice reduction (34816B)
    int   cnt[16 * 32];         // per-warp histograms
};

// ---------------------------------------------------------------------------
// k1: CTAs 0..63: partial GEMM1 (jt x ks = 16 x 4). CTAs 64..: histograms.
// ---------------------------------------------------------------------------
__global__ void __launch_bounds__(TPB, 1)
k1(const float* __restrict__ E, const float* __restrict__ W1,
   const int* __restrict__ tok, const int* __restrict__ cu, int n_segs) {
    __shared__ SmemU sm;
    const int bid = blockIdx.x;
    const int tid = threadIdx.x;

    if (bid < 64) {
        const int jt = bid >> 2;
        const int ks = bid & 3;
        const int tx = tid & 31;
        const int ty = tid >> 5;

        // stage E k-slice transposed: one float4 LDG per thread (+tail)
        const float4* E4 = (const float4*)E;
        if (tid < V * 32) {
            const int v = tid >> 5;
            const int q = tid & 31;
            const float4 e = E4[v * (D / 4) + ks * 32 + q];
            const int kl = q * 4;
            sm.etr[(kl + 0) * EPAD + v] = e.x;
            sm.etr[(kl + 1) * EPAD + v] = e.y;
            sm.etr[(kl + 2) * EPAD + v] = e.z;
            sm.etr[(kl + 3) * EPAD + v] = e.w;
        }
        if (tid < V * 32 - TPB) {
            const int i = TPB + tid;
            const int v = i >> 5;
            const int q = i & 31;
            const float4 e = E4[v * (D / 4) + ks * 32 + q];
            const int kl = q * 4;
            sm.etr[(kl + 0) * EPAD + v] = e.x;
            sm.etr[(kl + 1) * EPAD + v] = e.y;
            sm.etr[(kl + 2) * EPAD + v] = e.z;
            sm.etr[(kl + 3) * EPAD + v] = e.w;
        }
        __syncthreads();

        float acc[V];
#pragma unroll
        for (int v = 0; v < V; v++) acc[v] = 0.0f;

        const float* wp = W1 + (size_t)(ks * KSL + ty * 8) * D + jt * 32 + tx;
        float w[8];
#pragma unroll
        for (int kk = 0; kk < 8; kk++) w[kk] = wp[kk * D];

#pragma unroll
        for (int kk = 0; kk < 8; kk++) {
            const float* er = &sm.etr[(ty * 8 + kk) * EPAD];
            const float4 e0 = *(const float4*)(er);
            const float4 e1 = *(const float4*)(er + 4);
            const float4 e2 = *(const float4*)(er + 8);
            const float4 e3 = *(const float4*)(er + 12);
            const float  ee = er[16];
            const float  wv = w[kk];
            acc[0]  += e0.x * wv;  acc[1]  += e0.y * wv;
            acc[2]  += e0.z * wv;  acc[3]  += e0.w * wv;
            acc[4]  += e1.x * wv;  acc[5]  += e1.y * wv;
            acc[6]  += e1.z * wv;  acc[7]  += e1.w * wv;
            acc[8]  += e2.x * wv;  acc[9]  += e2.y * wv;
            acc[10] += e2.z * wv;  acc[11] += e2.w * wv;
            acc[12] += e3.x * wv;  acc[13] += e3.y * wv;
            acc[14] += e3.z * wv;  acc[15] += e3.w * wv;
            acc[16] += ee   * wv;
        }
        __syncthreads();

#pragma unroll
        for (int v = 0; v < V; v++) sm.red[(ty * V + v) * 32 + tx] = acc[v];
        __syncthreads();

        for (int o = tid; o < V * 32; o += TPB) {
            const int v = o >> 5;
            const int t = o & 31;
            float s = 0.0f;
#pragma unroll
            for (int sl = 0; sl < 16; sl++) s += sm.red[(sl * V + v) * 32 + t];
            g_part1[ks][v][jt * 32 + t] = s;
        }
        return;
    }

    const int s = bid - 64;
    if (s >= n_segs) return;
    const int start = cu[s];
    const int end = cu[s + 1];
    const int wid = tid >> 5;

    for (int i = tid; i < 16 * 32; i += TPB) sm.cnt[i] = 0;
    __syncthreads();
    for (int base = start + tid * 4; base < end; base += TPB * 4) {
        int t0 = -1, t1 = -1, t2 = -1, t3 = -1;
        if (base + 0 < end) t0 = tok[base + 0];
        if (base + 1 < end) t1 = tok[base + 1];
        if (base + 2 < end) t2 = tok[base + 2];
        if (base + 3 < end) t3 = tok[base + 3];
        if (t0 >= 0) atomicAdd(&sm.cnt[wid * 32 + t0], 1);
        if (t1 >= 0) atomicAdd(&sm.cnt[wid * 32 + t1], 1);
        if (t2 >= 0) atomicAdd(&sm.cnt[wid * 32 + t2], 1);
        if (t3 >= 0) atomicAdd(&sm.cnt[wid * 32 + t3], 1);
    }
    __syncthreads();
    if (tid < V) {
        int c = 0;
#pragma unroll
        for (int w = 0; w < 16; w++) c += sm.cnt[w * 32 + tid];
        g_hist[s][tid] = c;
    }
}

// ---------------------------------------------------------------------------
// kmid: finalize mid = gelu(E@W1+b1) into transposed padded g_midT[k*20+v].
// 17 CTAs x 512 threads = 8704 = V*D elements, one each.
// ---------------------------------------------------------------------------
__global__ void __launch_bounds__(TPB, 1)
kmid(const float* __restrict__ b1) {
    const int i = blockIdx.x * TPB + threadIdx.x;   // < V*D
    const int v = i >> 9;
    const int k = i & 511;
    float s = b1[k] + g_part1[0][v][k] + g_part1[1][v][k]
                    + g_part1[2][v][k] + g_part1[3][v][k];
    s = 0.5f * s * (1.0f + erff(s * 0.70710678118654752f));
    g_midT[k * EPAD + v] = s;
}

// ---------------------------------------------------------------------------
// k2: 64 CTAs x 8 output columns, full-K GEMM2 + mix + store. No partials.
// Thread layout: jl = tid & 7 (column), ty = tid >> 3 (k-group of 8).
// Static smem: 40960 + 2176 + 4608 + 256 = 48000 B (<= 49152).
// ---------------------------------------------------------------------------
__global__ void __launch_bounds__(TPB, 1)
k2(const float* __restrict__ W2, const float* __restrict__ b2,
   const int* __restrict__ cu, float* __restrict__ out, int n_segs) {
    __shared__ float etr[D * EPAD];            // 40960B; reused as red after sync
    __shared__ float Ht[V * 8 * 4];            // 2176B (extra slack)
    __shared__ float fcs[MAX_SEGS * 18];       // 4608B
    __shared__ float inv[MAX_SEGS];            // 256B

    const int bid = blockIdx.x;
    const int tid = threadIdx.x;
    const int jl = tid & 7;
    const int ty = tid >> 3;                   // 0..63
    const int jbase = bid * 8;

    // overlap: segment counts + inverse lengths (independent of GEMM)
    {
        const int i0 = tid, i1 = tid + TPB, i2 = tid + 2 * TPB;  // < 1152
        int c0 = 0, c1 = 0, c2 = 0;
        if (i0 < n_segs * V) c0 = ((const int*)g_hist)[i0];
        if (i1 < n_segs * V) c1 = ((const int*)g_hist)[i1];
        if (i2 < n_segs * V) c2 = ((const int*)g_hist)[i2];
        if (i0 < n_segs * V) fcs[(i0 / V) * 18 + (i0 % V)] = (float)c0;
        if (i1 < n_segs * V) fcs[(i1 / V) * 18 + (i1 % V)] = (float)c1;
        if (i2 < n_segs * V) fcs[(i2 / V) * 18 + (i2 % V)] = (float)c2;
        if (tid < n_segs) inv[tid] = 1.0f / (float)(cu[tid + 1] - cu[tid]);
    }

    // stage full transposed mid table: 5 fixed float4 LDG per thread
    {
        const float4* M4 = (const float4*)g_midT;   // 2560 float4
        float4* S4 = (float4*)etr;
        const float4 m0 = M4[tid];
        const float4 m1 = M4[tid + 512];
        const float4 m2 = M4[tid + 1024];
        const float4 m3 = M4[tid + 1536];
        const float4 m4 = M4[tid + 2048];
        S4[tid] = m0;  S4[tid + 512] = m1;  S4[tid + 1024] = m2;
        S4[tid + 1536] = m3;  S4[tid + 2048] = m4;
    }
    __syncthreads();

    float acc[V];
#pragma unroll
    for (int v = 0; v < V; v++) acc[v] = 0.0f;

    const float* wp = W2 + (size_t)(ty * 8) * D + jbase + jl;
    float w[8];
#pragma unroll
    for (int kk = 0; kk < 8; kk++) w[kk] = wp[kk * D];

#pragma unroll
    for (int kk = 0; kk < 8; kk++) {
        const float* er = &etr[(ty * 8 + kk) * EPAD];
        const float4 e0 = *(const float4*)(er);
        const float4 e1 = *(const float4*)(er + 4);
        const float4 e2 = *(const float4*)(er + 8);
        const float4 e3 = *(const float4*)(er + 12);
        const float  ee = er[16];
        const float  wv = w[kk];
        acc[0]  += e0.x * wv;  acc[1]  += e0.y * wv;
        acc[2]  += e0.z * wv;  acc[3]  += e0.w * wv;
        acc[4]  += e1.x * wv;  acc[5]  += e1.y * wv;
        acc[6]  += e1.z * wv;  acc[7]  += e1.w * wv;
        acc[8]  += e2.x * wv;  acc[9]  += e2.y * wv;
        acc[10] += e2.z * wv;  acc[11] += e2.w * wv;
        acc[12] += e3.x * wv;  acc[13] += e3.y * wv;
        acc[14] += e3.z * wv;  acc[15] += e3.w * wv;
        acc[16] += ee   * wv;
    }
    __syncthreads();           // done reading etr; reuse as reduction buffer

    float* red = etr;          // [64][17][8] = 8704 floats, fits in 10240
#pragma unroll
    for (int v = 0; v < V; v++) red[(ty * V + v) * 8 + jl] = acc[v];
    __syncthreads();

    // 136 outputs (v, jl); fixed 64-term sum order -> deterministic
    if (tid < V * 8) {
        float s = b2[jbase + (tid & 7)];
#pragma unroll
        for (int g = 0; g < 64; g++) s += red[g * (V * 8) + tid];
        Ht[tid] = s;
    }
    __syncthreads();

    // mix: thread = (segment, column); 64*8 = 512 outputs exactly
    const int s = tid >> 3;
    if (s < n_segs) {
        const float* f = &fcs[s * 18];
        float a = 0.0f;
#pragma unroll
        for (int v = 0; v < V; v++) a += f[v] * Ht[v * 8 + jl];
        out[s * D + jbase + jl] = a * inv[s];
    }
}

// ---------------------------------------------------------------------------
extern "C" void kernel_launch(void* const* d_in, const int* in_sizes, int n_in,
                              void* d_out, int out_size) {
    const int*   tok = (const int*)  d_in[0];
    const int*   cu  = (const int*)  d_in[1];
    const float* E   = (const float*)d_in[2];
    const float* W1  = (const float*)d_in[3];
    const float* b1  = (const float*)d_in[4];
    const float* W2  = (const float*)d_in[5];
    const float* b2  = (const float*)d_in[6];
    float*       out = (float*)d_out;

    int n_segs = in_sizes[1] - 1;
    if (n_segs > MAX_SEGS) n_segs = MAX_SEGS;

    k1<<<64 + n_segs, TPB>>>(E, W1, tok, cu, n_segs);
    kmid<<<V, TPB>>>(b1);
    k2<<<64, TPB>>>(W2, b2, cu, out, n_segs);
}